// round 2
// baseline (speedup 1.0000x reference)
#include <cuda_runtime.h>
#include <cuda_bf16.h>
#include <cstdint>

// Problem constants
#define BATCH   2048
#define NTOK    98
#define CDIM    128
#define NHEADS  4
#define HD      32
#define LWIN    512
#define MROWS   (BATCH * NTOK)          // 200704
#define QKVCOLS (3 * CDIM)              // 384
#define RELM    507                     // 3*13*13

// Scratch (allocation-free rule: __device__ globals)
__device__ float g_qkv[(size_t)MROWS * QKVCOLS];   // [B*N, 3*H*HD] row = [3][H][32]
__device__ float g_ctx[(size_t)MROWS * CDIM];      // [B, N, H*HD]
__device__ float g_bias[NHEADS * NTOK * NTOK];     // [h][n][m]

// ---------------------------------------------------------------------------
// Kernel 0: materialize rel-pos bias table  bias[h][n][m] = rpe[h][relidx(n,m)]
// ---------------------------------------------------------------------------
__global__ void bias_kernel(const float* __restrict__ rpe) {
    int idx = blockIdx.x * blockDim.x + threadIdx.x;
    const int total = NHEADS * NTOK * NTOK;
    if (idx >= total) return;
    int m = idx % NTOK;
    int n = (idx / NTOK) % NTOK;
    int h = idx / (NTOK * NTOK);
    int tn = n / 49, rn = n % 49, hn = rn / 7, wn = rn % 7;
    int tm = m / 49, rm = m % 49, hm = rm / 7, wm = rm % 7;
    int rel = (tn - tm + 1) * 169 + (hn - hm + 6) * 13 + (wn - wm + 6);
    g_bias[idx] = rpe[h * RELM + rel];
}

// ---------------------------------------------------------------------------
// Tiled SGEMM: C[M,N] = A[M,K] @ W[N,K]^T + bias[N]
// BM=BN=64, BK=64, 256 threads, 4x4 micro-tile per thread.
// Smem tiles stored transposed [k][m]/[k][n] with pitch 68 (float4-aligned,
// low-conflict). Requires M%64==0, N%64==0, K%64==0 (true here).
// ---------------------------------------------------------------------------
__global__ void __launch_bounds__(256)
gemm_bias_kernel(const float* __restrict__ A, const float* __restrict__ W,
                 const float* __restrict__ bias, float* __restrict__ C,
                 int M, int N, int K) {
    __shared__ float As[64 * 68];
    __shared__ float Ws[64 * 68];

    const int bm = blockIdx.x * 64;
    const int bn = blockIdx.y * 64;
    const int tid = threadIdx.x;
    const int tx = tid & 15;
    const int ty = tid >> 4;

    float acc[4][4];
#pragma unroll
    for (int i = 0; i < 4; i++)
#pragma unroll
        for (int j = 0; j < 4; j++) acc[i][j] = 0.f;

    for (int k0 = 0; k0 < K; k0 += 64) {
#pragma unroll
        for (int i = 0; i < 4; i++) {
            int pos = tid + i * 256;      // 0..1023 float4 slots
            int row = pos >> 4;           // 0..63
            int c4  = pos & 15;           // 0..15
            float4 av = *(const float4*)(A + (size_t)(bm + row) * K + k0 + c4 * 4);
            As[(c4 * 4 + 0) * 68 + row] = av.x;
            As[(c4 * 4 + 1) * 68 + row] = av.y;
            As[(c4 * 4 + 2) * 68 + row] = av.z;
            As[(c4 * 4 + 3) * 68 + row] = av.w;
            float4 wv = *(const float4*)(W + (size_t)(bn + row) * K + k0 + c4 * 4);
            Ws[(c4 * 4 + 0) * 68 + row] = wv.x;
            Ws[(c4 * 4 + 1) * 68 + row] = wv.y;
            Ws[(c4 * 4 + 2) * 68 + row] = wv.z;
            Ws[(c4 * 4 + 3) * 68 + row] = wv.w;
        }
        __syncthreads();

#pragma unroll 8
        for (int k = 0; k < 64; k++) {
            float4 a4 = *(const float4*)(&As[k * 68 + ty * 4]);
            float4 w4 = *(const float4*)(&Ws[k * 68 + tx * 4]);
            float a[4] = {a4.x, a4.y, a4.z, a4.w};
            float w[4] = {w4.x, w4.y, w4.z, w4.w};
#pragma unroll
            for (int i = 0; i < 4; i++)
#pragma unroll
                for (int j = 0; j < 4; j++) acc[i][j] = fmaf(a[i], w[j], acc[i][j]);
        }
        __syncthreads();
    }

#pragma unroll
    for (int i = 0; i < 4; i++) {
        int row = bm + ty * 4 + i;
#pragma unroll
        for (int j = 0; j < 4; j++) {
            int col = bn + tx * 4 + j;
            C[(size_t)row * N + col] = acc[i][j] + bias[col];
        }
    }
}

// ---------------------------------------------------------------------------
// Kernel 2: attention for one (b, h) per block. 128 threads, thread n owns
// query row n (n < 98). K/V staged in smem; scores in pitch-99 smem rows.
// ---------------------------------------------------------------------------
__global__ void __launch_bounds__(128)
attn_kernel(const float* __restrict__ qkv, const float* __restrict__ mask,
            float* __restrict__ ctx) {
    extern __shared__ float sm[];
    float* ks = sm;                 // [98][32]
    float* vs = sm + NTOK * HD;     // [98][32]
    float* sc = sm + 2 * NTOK * HD; // [98][99]

    const int b = blockIdx.x;
    const int h = blockIdx.y;
    const int tid = threadIdx.x;

    const float* base = qkv + (size_t)b * NTOK * QKVCOLS + h * HD;

    // cooperative K/V load: 98*32/4 = 784 float4 each
    for (int i = tid; i < NTOK * HD / 4; i += 128) {
        int m = i >> 3;       // /8 (32 floats = 8 float4 per row)
        int d4 = i & 7;
        float4 kv = *(const float4*)(base + (size_t)m * QKVCOLS + CDIM + d4 * 4);
        *(float4*)(ks + m * HD + d4 * 4) = kv;
        float4 vv = *(const float4*)(base + (size_t)m * QKVCOLS + 2 * CDIM + d4 * 4);
        *(float4*)(vs + m * HD + d4 * 4) = vv;
    }
    __syncthreads();

    if (tid < NTOK) {
        const int n = tid;
        const float scale = 0.17677669529663687f;  // 32^-0.5
        float q[HD];
#pragma unroll
        for (int d = 0; d < HD; d++) q[d] = base[(size_t)n * QKVCOLS + d] * scale;

        const float* mrow = mask + ((size_t)(b & (LWIN - 1)) * NTOK + n) * NTOK;
        const float* brow = g_bias + ((size_t)h * NTOK + n) * NTOK;
        float* srow = sc + n * 99;

        float mx = -1e30f;
        for (int m = 0; m < NTOK; m++) {
            float s = 0.f;
#pragma unroll
            for (int d = 0; d < HD; d++) s = fmaf(q[d], ks[m * HD + d], s);
            s += brow[m] + mrow[m];
            srow[m] = s;
            mx = fmaxf(mx, s);
        }

        float sum = 0.f;
        for (int m = 0; m < NTOK; m++) {
            float p = __expf(srow[m] - mx);
            srow[m] = p;
            sum += p;
        }
        float inv = 1.f / sum;

        float out[HD];
#pragma unroll
        for (int d = 0; d < HD; d++) out[d] = 0.f;
        for (int m = 0; m < NTOK; m++) {
            float p = srow[m];
#pragma unroll
            for (int d = 0; d < HD; d++) out[d] = fmaf(p, vs[m * HD + d], out[d]);
        }

        float* crow = ctx + ((size_t)b * NTOK + n) * CDIM + h * HD;
#pragma unroll
        for (int d = 0; d < HD; d++) crow[d] = out[d] * inv;
    }
}

// ---------------------------------------------------------------------------
// Launch
// ---------------------------------------------------------------------------
extern "C" void kernel_launch(void* const* d_in, const int* in_sizes, int n_in,
                              void* d_out, int out_size) {
    const float* x      = (const float*)d_in[0];
    const float* mask   = (const float*)d_in[1];
    const float* qkv_w  = (const float*)d_in[2];
    const float* qkv_b  = (const float*)d_in[3];
    const float* rpe    = (const float*)d_in[4];
    const float* proj_w = (const float*)d_in[5];
    const float* proj_b = (const float*)d_in[6];
    float* out = (float*)d_out;

    float *qkv_buf, *ctx_buf;
    cudaGetSymbolAddress((void**)&qkv_buf, g_qkv);
    cudaGetSymbolAddress((void**)&ctx_buf, g_ctx);

    // 0) bias table
    {
        int total = NHEADS * NTOK * NTOK;
        bias_kernel<<<(total + 255) / 256, 256>>>(rpe);
    }
    // 1) QKV GEMM: [200704,128] @ [384,128]^T
    {
        dim3 grid(MROWS / 64, QKVCOLS / 64);
        gemm_bias_kernel<<<grid, 256>>>(x, qkv_w, qkv_b, qkv_buf,
                                        MROWS, QKVCOLS, CDIM);
    }
    // 2) attention
    {
        int smem = (2 * NTOK * HD + NTOK * 99) * (int)sizeof(float);  // 63896 B
        cudaFuncSetAttribute(attn_kernel,
                             cudaFuncAttributeMaxDynamicSharedMemorySize, smem);
        dim3 grid(BATCH, NHEADS);
        attn_kernel<<<grid, 128, smem>>>(qkv_buf, mask, ctx_buf);
    }
    // 3) projection GEMM: [200704,128] @ [128,128]^T -> d_out
    {
        dim3 grid(MROWS / 64, CDIM / 64);
        gemm_bias_kernel<<<grid, 256>>>(ctx_buf, proj_w, proj_b, out,
                                        MROWS, CDIM, CDIM);
    }
}

// round 8
// speedup vs baseline: 2.0246x; 2.0246x over previous
#include <cuda_runtime.h>
#include <cuda_bf16.h>
#include <cstdint>

// Problem constants
#define BATCH   2048
#define NTOK    98
#define CDIM    128
#define NHEADS  4
#define HD      32
#define LWIN    512
#define MROWS   (BATCH * NTOK)          // 200704
#define QKVCOLS (3 * CDIM)              // 384
#define RELM    507                     // 3*13*13

// Scratch (allocation-free rule: __device__ globals)
__device__ float g_qkv[(size_t)MROWS * QKVCOLS];   // [B*N, 3*H*HD]
__device__ float g_ctx[(size_t)MROWS * CDIM];      // [B, N, H*HD]
__device__ float g_bias[NHEADS * NTOK * NTOK];     // [h][n][m]

__device__ __forceinline__ uint32_t f2tf32(float f) {
    uint32_t u;
    asm("cvt.rna.tf32.f32 %0, %1;" : "=r"(u) : "f"(f));
    return u;
}

// ---------------------------------------------------------------------------
// Kernel 0: rel-pos bias table
// ---------------------------------------------------------------------------
__global__ void bias_kernel(const float* __restrict__ rpe) {
    int idx = blockIdx.x * blockDim.x + threadIdx.x;
    const int total = NHEADS * NTOK * NTOK;
    if (idx >= total) return;
    int m = idx % NTOK;
    int n = (idx / NTOK) % NTOK;
    int h = idx / (NTOK * NTOK);
    int tn = n / 49, rn = n % 49, hn = rn / 7, wn = rn % 7;
    int tm = m / 49, rm = m % 49, hm = rm / 7, wm = rm % 7;
    int rel = (tn - tm + 1) * 169 + (hn - hm + 6) * 13 + (wn - wm + 6);
    g_bias[idx] = rpe[h * RELM + rel];
}

// ---------------------------------------------------------------------------
// tf32 mma.sync GEMM: C[M,Ntot] = A[M,128] @ W[Ntot,128]^T + bias[Ntot]
// CTA: 128-row M tile, loops over 64-col n-tiles. 256 threads = 8 warps,
// warp tile 32x32 (2x4 m16n8k8 mma tiles, 16 k-steps of 8).
// Smem pitch 132 floats -> conflict-free fragment LDS.
// ---------------------------------------------------------------------------
#define AP 132
#define AS_FLOATS (128 * AP)
#define WS_FLOATS (64 * AP)
#define GSMEM ((AS_FLOATS + WS_FLOATS) * 4)   // 101376 bytes

extern __shared__ char smem_raw[];

__device__ __forceinline__ void mma_tf32(float& c0, float& c1, float& c2, float& c3,
                                         uint32_t a0, uint32_t a1, uint32_t a2, uint32_t a3,
                                         uint32_t b0, uint32_t b1) {
    asm volatile(
        "mma.sync.aligned.m16n8k8.row.col.f32.tf32.tf32.f32 "
        "{%0,%1,%2,%3}, {%4,%5,%6,%7}, {%8,%9}, {%0,%1,%2,%3};"
        : "+f"(c0), "+f"(c1), "+f"(c2), "+f"(c3)
        : "r"(a0), "r"(a1), "r"(a2), "r"(a3), "r"(b0), "r"(b1));
}

__global__ void __launch_bounds__(256)
gemm_tf32_kernel(const float* __restrict__ A, const float* __restrict__ W,
                 const float* __restrict__ bias, float* __restrict__ C,
                 int Ntot) {
    uint32_t* As = (uint32_t*)smem_raw;            // [128][AP] tf32 bits
    uint32_t* Ws = (uint32_t*)smem_raw + AS_FLOATS; // [64][AP]

    const int tid = threadIdx.x;
    const int wid = tid >> 5;
    const int lane = tid & 31;
    const int g = lane >> 2;           // 0..7
    const int t4 = lane & 3;           // 0..3
    const int mw = (wid & 3) * 32;     // warp m offset in tile
    const int nw = (wid >> 2) * 32;    // warp n offset in tile
    const int bm = blockIdx.x * 128;
    const int nt = Ntot >> 6;

    // Stage A tile: 128x128, converted to tf32 (rna)
    for (int i = 0; i < 16; i++) {
        int idx = tid + i * 256;       // 0..4095 float4 slots
        int row = idx >> 5;
        int c4 = idx & 31;
        float4 v = *(const float4*)(A + (size_t)(bm + row) * CDIM + c4 * 4);
        uint4 t;
        t.x = f2tf32(v.x); t.y = f2tf32(v.y); t.z = f2tf32(v.z); t.w = f2tf32(v.w);
        *(uint4*)(As + row * AP + c4 * 4) = t;
    }

    for (int t = 0; t < nt; t++) {
        const int bn = t * 64;
        // Stage B tile: 64 rows (n) x 128 cols (k)
        for (int i = 0; i < 8; i++) {
            int idx = tid + i * 256;   // 0..2047
            int row = idx >> 5;
            int c4 = idx & 31;
            float4 v = *(const float4*)(W + (size_t)(bn + row) * CDIM + c4 * 4);
            uint4 u;
            u.x = f2tf32(v.x); u.y = f2tf32(v.y); u.z = f2tf32(v.z); u.w = f2tf32(v.w);
            *(uint4*)(Ws + row * AP + c4 * 4) = u;
        }
        __syncthreads();

        float acc[2][4][4];
#pragma unroll
        for (int mi = 0; mi < 2; mi++)
#pragma unroll
            for (int ni = 0; ni < 4; ni++)
#pragma unroll
                for (int r = 0; r < 4; r++) acc[mi][ni][r] = 0.f;

        const uint32_t* a_base0 = As + (mw + g) * AP + t4;
        const uint32_t* a_base1 = As + (mw + 16 + g) * AP + t4;
        const uint32_t* b_base = Ws + (nw + g) * AP + t4;

#pragma unroll
        for (int k0 = 0; k0 < 128; k0 += 8) {
            uint32_t a[2][4];
            a[0][0] = a_base0[k0];           a[0][1] = a_base0[8 * AP + k0];
            a[0][2] = a_base0[k0 + 4];       a[0][3] = a_base0[8 * AP + k0 + 4];
            a[1][0] = a_base1[k0];           a[1][1] = a_base1[8 * AP + k0];
            a[1][2] = a_base1[k0 + 4];       a[1][3] = a_base1[8 * AP + k0 + 4];
            uint32_t b[4][2];
#pragma unroll
            for (int ni = 0; ni < 4; ni++) {
                b[ni][0] = b_base[ni * 8 * AP + k0];
                b[ni][1] = b_base[ni * 8 * AP + k0 + 4];
            }
#pragma unroll
            for (int mi = 0; mi < 2; mi++)
#pragma unroll
                for (int ni = 0; ni < 4; ni++)
                    mma_tf32(acc[mi][ni][0], acc[mi][ni][1], acc[mi][ni][2], acc[mi][ni][3],
                             a[mi][0], a[mi][1], a[mi][2], a[mi][3],
                             b[ni][0], b[ni][1]);
        }

        // Epilogue: +bias, direct store (c0,c1 / c2,c3 are col pairs)
#pragma unroll
        for (int mi = 0; mi < 2; mi++) {
            int row0 = bm + mw + mi * 16 + g;
#pragma unroll
            for (int ni = 0; ni < 4; ni++) {
                int col = bn + nw + ni * 8 + 2 * t4;
                float b0 = bias[col], b1 = bias[col + 1];
                float2 v0 = make_float2(acc[mi][ni][0] + b0, acc[mi][ni][1] + b1);
                float2 v1 = make_float2(acc[mi][ni][2] + b0, acc[mi][ni][3] + b1);
                *(float2*)(C + (size_t)row0 * Ntot + col) = v0;
                *(float2*)(C + (size_t)(row0 + 8) * Ntot + col) = v1;
            }
        }
        __syncthreads();
    }
}

// ---------------------------------------------------------------------------
// Attention: one (b,h) per block, thread n owns query row n. float4-vectorized.
// ---------------------------------------------------------------------------
__global__ void __launch_bounds__(128)
attn_kernel(const float* __restrict__ qkv, const float* __restrict__ mask,
            float* __restrict__ ctx) {
    float* sm = (float*)smem_raw;
    float* ks = sm;                 // [98][32]
    float* vs = sm + NTOK * HD;     // [98][32]
    float* sc = sm + 2 * NTOK * HD; // [98][99]

    const int b = blockIdx.x;
    const int h = blockIdx.y;
    const int tid = threadIdx.x;

    const float* base = qkv + (size_t)b * NTOK * QKVCOLS + h * HD;

    for (int i = tid; i < NTOK * HD / 4; i += 128) {
        int m = i >> 3;
        int d4 = i & 7;
        *(float4*)(ks + m * HD + d4 * 4) =
            *(const float4*)(base + (size_t)m * QKVCOLS + CDIM + d4 * 4);
        *(float4*)(vs + m * HD + d4 * 4) =
            *(const float4*)(base + (size_t)m * QKVCOLS + 2 * CDIM + d4 * 4);
    }
    __syncthreads();

    if (tid < NTOK) {
        const int n = tid;
        const float scale = 0.17677669529663687f;  // 32^-0.5
        float4 qv[8];
#pragma unroll
        for (int j = 0; j < 8; j++) {
            float4 q = *(const float4*)(base + (size_t)n * QKVCOLS + j * 4);
            qv[j].x = q.x * scale; qv[j].y = q.y * scale;
            qv[j].z = q.z * scale; qv[j].w = q.w * scale;
        }

        const float* mrow = mask + ((size_t)(b & (LWIN - 1)) * NTOK + n) * NTOK;
        const float* brow = g_bias + ((size_t)h * NTOK + n) * NTOK;
        float* srow = sc + n * 99;

        float mx = -1e30f;
#pragma unroll 2
        for (int m = 0; m < NTOK; m++) {
            const float4* krow = (const float4*)(ks + m * HD);
            float s0 = 0.f, s1 = 0.f;
#pragma unroll
            for (int j = 0; j < 8; j += 2) {
                float4 k0 = krow[j], k1 = krow[j + 1];
                s0 = fmaf(qv[j].x, k0.x, s0); s0 = fmaf(qv[j].y, k0.y, s0);
                s0 = fmaf(qv[j].z, k0.z, s0); s0 = fmaf(qv[j].w, k0.w, s0);
                s1 = fmaf(qv[j + 1].x, k1.x, s1); s1 = fmaf(qv[j + 1].y, k1.y, s1);
                s1 = fmaf(qv[j + 1].z, k1.z, s1); s1 = fmaf(qv[j + 1].w, k1.w, s1);
            }
            float s = s0 + s1 + brow[m] + mrow[m];
            srow[m] = s;
            mx = fmaxf(mx, s);
        }

        float sum = 0.f;
        for (int m = 0; m < NTOK; m++) {
            float p = __expf(srow[m] - mx);
            srow[m] = p;
            sum += p;
        }
        float inv = 1.f / sum;

        float4 o[8];
#pragma unroll
        for (int j = 0; j < 8; j++) o[j] = make_float4(0.f, 0.f, 0.f, 0.f);
#pragma unroll 2
        for (int m = 0; m < NTOK; m++) {
            float p = srow[m];
            const float4* vrow = (const float4*)(vs + m * HD);
#pragma unroll
            for (int j = 0; j < 8; j++) {
                float4 v = vrow[j];
                o[j].x = fmaf(p, v.x, o[j].x);
                o[j].y = fmaf(p, v.y, o[j].y);
                o[j].z = fmaf(p, v.z, o[j].z);
                o[j].w = fmaf(p, v.w, o[j].w);
            }
        }

        float* crow = ctx + ((size_t)b * NTOK + n) * CDIM + h * HD;
#pragma unroll
        for (int j = 0; j < 8; j++) {
            float4 w;
            w.x = o[j].x * inv; w.y = o[j].y * inv;
            w.z = o[j].z * inv; w.w = o[j].w * inv;
            *(float4*)(crow + j * 4) = w;
        }
    }
}

// ---------------------------------------------------------------------------
// Launch
// ---------------------------------------------------------------------------
extern "C" void kernel_launch(void* const* d_in, const int* in_sizes, int n_in,
                              void* d_out, int out_size) {
    const float* x      = (const float*)d_in[0];
    const float* mask   = (const float*)d_in[1];
    const float* qkv_w  = (const float*)d_in[2];
    const float* qkv_b  = (const float*)d_in[3];
    const float* rpe    = (const float*)d_in[4];
    const float* proj_w = (const float*)d_in[5];
    const float* proj_b = (const float*)d_in[6];
    float* out = (float*)d_out;

    float *qkv_buf, *ctx_buf;
    cudaGetSymbolAddress((void**)&qkv_buf, g_qkv);
    cudaGetSymbolAddress((void**)&ctx_buf, g_ctx);

    const int asmem = (2 * NTOK * HD + NTOK * 99) * (int)sizeof(float);  // 63896
    cudaFuncSetAttribute(gemm_tf32_kernel,
                         cudaFuncAttributeMaxDynamicSharedMemorySize, GSMEM);
    cudaFuncSetAttribute(attn_kernel,
                         cudaFuncAttributeMaxDynamicSharedMemorySize, asmem);

    // 0) bias table
    {
        int total = NHEADS * NTOK * NTOK;
        bias_kernel<<<(total + 255) / 256, 256>>>(rpe);
    }
    // 1) QKV GEMM (tf32 mma.sync): [200704,128] @ [384,128]^T
    gemm_tf32_kernel<<<MROWS / 128, 256, GSMEM>>>(x, qkv_w, qkv_b, qkv_buf, QKVCOLS);
    // 2) attention
    {
        dim3 grid(BATCH, NHEADS);
        attn_kernel<<<grid, 128, asmem>>>(qkv_buf, mask, ctx_buf);
    }
    // 3) projection GEMM (tf32): [200704,128] @ [128,128]^T -> d_out
    gemm_tf32_kernel<<<MROWS / 128, 256, GSMEM>>>(ctx_buf, proj_w, proj_b, out, CDIM);
}

// round 9
// speedup vs baseline: 2.0266x; 1.0010x over previous
#include <cuda_runtime.h>
#include <cuda_bf16.h>
#include <cstdint>

// Problem constants
#define BATCH   2048
#define NTOK    98
#define CDIM    128
#define NHEADS  4
#define HD      32
#define LWIN    512
#define MROWS   (BATCH * NTOK)          // 200704
#define QKVCOLS (3 * CDIM)              // 384
#define RELM    507                     // 3*13*13

// Scratch (allocation-free rule: __device__ globals)
__device__ float g_qkv[(size_t)MROWS * QKVCOLS];   // [B*N, 3*H*HD]
__device__ float g_ctx[(size_t)MROWS * CDIM];      // [B, N, H*HD]
__device__ float g_bias[NHEADS * NTOK * NTOK];     // [h][n][m]

__device__ __forceinline__ uint32_t f2tf32(float f) {
    uint32_t u;
    asm("cvt.rna.tf32.f32 %0, %1;" : "=r"(u) : "f"(f));
    return u;
}

extern __shared__ char smem_raw[];

__device__ __forceinline__ void mma_tf32(float& c0, float& c1, float& c2, float& c3,
                                         uint32_t a0, uint32_t a1, uint32_t a2, uint32_t a3,
                                         uint32_t b0, uint32_t b1) {
    asm volatile(
        "mma.sync.aligned.m16n8k8.row.col.f32.tf32.tf32.f32 "
        "{%0,%1,%2,%3}, {%4,%5,%6,%7}, {%8,%9}, {%0,%1,%2,%3};"
        : "+f"(c0), "+f"(c1), "+f"(c2), "+f"(c3)
        : "r"(a0), "r"(a1), "r"(a2), "r"(a3), "r"(b0), "r"(b1));
}

// ---------------------------------------------------------------------------
// Kernel 0: rel-pos bias table
// ---------------------------------------------------------------------------
__global__ void bias_kernel(const float* __restrict__ rpe) {
    int idx = blockIdx.x * blockDim.x + threadIdx.x;
    const int total = NHEADS * NTOK * NTOK;
    if (idx >= total) return;
    int m = idx % NTOK;
    int n = (idx / NTOK) % NTOK;
    int h = idx / (NTOK * NTOK);
    int tn = n / 49, rn = n % 49, hn = rn / 7, wn = rn % 7;
    int tm = m / 49, rm = m % 49, hm = rm / 7, wm = rm % 7;
    int rel = (tn - tm + 1) * 169 + (hn - hm + 6) * 13 + (wn - wm + 6);
    g_bias[idx] = rpe[h * RELM + rel];
}

// ---------------------------------------------------------------------------
// tf32 mma.sync GEMM: C[M,Ntot] = A[M,128] @ W[Ntot,128]^T + bias[Ntot]
// ---------------------------------------------------------------------------
#define AP 132
#define AS_FLOATS (128 * AP)
#define WS_FLOATS (64 * AP)
#define GSMEM ((AS_FLOATS + WS_FLOATS) * 4)   // 101376 bytes

__global__ void __launch_bounds__(256)
gemm_tf32_kernel(const float* __restrict__ A, const float* __restrict__ W,
                 const float* __restrict__ bias, float* __restrict__ C,
                 int Ntot) {
    uint32_t* As = (uint32_t*)smem_raw;             // [128][AP] tf32 bits
    uint32_t* Ws = (uint32_t*)smem_raw + AS_FLOATS; // [64][AP]

    const int tid = threadIdx.x;
    const int wid = tid >> 5;
    const int lane = tid & 31;
    const int g = lane >> 2;
    const int t4 = lane & 3;
    const int mw = (wid & 3) * 32;
    const int nw = (wid >> 2) * 32;
    const int bm = blockIdx.x * 128;
    const int nt = Ntot >> 6;

    for (int i = 0; i < 16; i++) {
        int idx = tid + i * 256;
        int row = idx >> 5;
        int c4 = idx & 31;
        float4 v = *(const float4*)(A + (size_t)(bm + row) * CDIM + c4 * 4);
        uint4 t;
        t.x = f2tf32(v.x); t.y = f2tf32(v.y); t.z = f2tf32(v.z); t.w = f2tf32(v.w);
        *(uint4*)(As + row * AP + c4 * 4) = t;
    }

    for (int t = 0; t < nt; t++) {
        const int bn = t * 64;
        for (int i = 0; i < 8; i++) {
            int idx = tid + i * 256;
            int row = idx >> 5;
            int c4 = idx & 31;
            float4 v = *(const float4*)(W + (size_t)(bn + row) * CDIM + c4 * 4);
            uint4 u;
            u.x = f2tf32(v.x); u.y = f2tf32(v.y); u.z = f2tf32(v.z); u.w = f2tf32(v.w);
            *(uint4*)(Ws + row * AP + c4 * 4) = u;
        }
        __syncthreads();

        float acc[2][4][4];
#pragma unroll
        for (int mi = 0; mi < 2; mi++)
#pragma unroll
            for (int ni = 0; ni < 4; ni++)
#pragma unroll
                for (int r = 0; r < 4; r++) acc[mi][ni][r] = 0.f;

        const uint32_t* a_base0 = As + (mw + g) * AP + t4;
        const uint32_t* a_base1 = As + (mw + 16 + g) * AP + t4;
        const uint32_t* b_base = Ws + (nw + g) * AP + t4;

#pragma unroll
        for (int k0 = 0; k0 < 128; k0 += 8) {
            uint32_t a[2][4];
            a[0][0] = a_base0[k0];           a[0][1] = a_base0[8 * AP + k0];
            a[0][2] = a_base0[k0 + 4];       a[0][3] = a_base0[8 * AP + k0 + 4];
            a[1][0] = a_base1[k0];           a[1][1] = a_base1[8 * AP + k0];
            a[1][2] = a_base1[k0 + 4];       a[1][3] = a_base1[8 * AP + k0 + 4];
            uint32_t b[4][2];
#pragma unroll
            for (int ni = 0; ni < 4; ni++) {
                b[ni][0] = b_base[ni * 8 * AP + k0];
                b[ni][1] = b_base[ni * 8 * AP + k0 + 4];
            }
#pragma unroll
            for (int mi = 0; mi < 2; mi++)
#pragma unroll
                for (int ni = 0; ni < 4; ni++)
                    mma_tf32(acc[mi][ni][0], acc[mi][ni][1], acc[mi][ni][2], acc[mi][ni][3],
                             a[mi][0], a[mi][1], a[mi][2], a[mi][3],
                             b[ni][0], b[ni][1]);
        }

#pragma unroll
        for (int mi = 0; mi < 2; mi++) {
            int row0 = bm + mw + mi * 16 + g;
#pragma unroll
            for (int ni = 0; ni < 4; ni++) {
                int col = bn + nw + ni * 8 + 2 * t4;
                float b0 = bias[col], b1 = bias[col + 1];
                float2 v0 = make_float2(acc[mi][ni][0] + b0, acc[mi][ni][1] + b1);
                float2 v1 = make_float2(acc[mi][ni][2] + b0, acc[mi][ni][3] + b1);
                *(float2*)(C + (size_t)row0 * Ntot + col) = v0;
                *(float2*)(C + (size_t)(row0 + 8) * Ntot + col) = v1;
            }
        }
        __syncthreads();
    }
}

// ---------------------------------------------------------------------------
// Tensor-core attention: one CTA (128 thr, 4 warps) per (b,h).
// S = Q·K^T (M pad 128, N pad 104, K=32) -> smem; softmax rows in place;
// out = P·V (M pad 128, N=32, K pad 104) -> ctx.
// ---------------------------------------------------------------------------
#define QP 36
#define KP 36
#define VP 36
#define PP 108
#define QS_OFF 0
#define KS_OFF (128 * QP)                  // 4608
#define VS_OFF (KS_OFF + 104 * KP)         // 8352
#define PS_OFF (VS_OFF + 104 * VP)         // 12096
#define ASMEM  ((PS_OFF + 128 * PP) * 4)   // 103680 bytes

__global__ void __launch_bounds__(128)
attn_mma_kernel(const float* __restrict__ qkv, const float* __restrict__ mask,
                float* __restrict__ ctx) {
    uint32_t* Qs = (uint32_t*)smem_raw + QS_OFF;
    uint32_t* Ks = (uint32_t*)smem_raw + KS_OFF;
    uint32_t* Vs = (uint32_t*)smem_raw + VS_OFF;
    uint32_t* Ps = (uint32_t*)smem_raw + PS_OFF;

    const int b = blockIdx.x;
    const int h = blockIdx.y;
    const int tid = threadIdx.x;
    const int wid = tid >> 5;
    const int lane = tid & 31;
    const int g = lane >> 2;
    const int t4 = lane & 3;
    const int mw = wid * 32;
    const float scale = 0.17677669529663687f;  // 32^-0.5

    const float* qbase = qkv + (size_t)b * NTOK * QKVCOLS + h * HD;

    // Stage Q (scaled, rows padded to 128 with zeros)
    for (int i = tid; i < 128 * 8; i += 128) {
        int row = i >> 3;
        int c4 = (i & 7) * 4;
        uint4 t = make_uint4(0u, 0u, 0u, 0u);
        if (row < NTOK) {
            float4 v = *(const float4*)(qbase + (size_t)row * QKVCOLS + c4);
            t.x = f2tf32(v.x * scale); t.y = f2tf32(v.y * scale);
            t.z = f2tf32(v.z * scale); t.w = f2tf32(v.w * scale);
        }
        *(uint4*)(Qs + row * QP + c4) = t;
    }
    // Stage K, V (rows padded to 104 with zeros)
    for (int i = tid; i < 104 * 8; i += 128) {
        int row = i >> 3;
        int c4 = (i & 7) * 4;
        uint4 tk = make_uint4(0u, 0u, 0u, 0u);
        uint4 tv = make_uint4(0u, 0u, 0u, 0u);
        if (row < NTOK) {
            float4 kv = *(const float4*)(qbase + (size_t)row * QKVCOLS + CDIM + c4);
            tk.x = f2tf32(kv.x); tk.y = f2tf32(kv.y); tk.z = f2tf32(kv.z); tk.w = f2tf32(kv.w);
            float4 vv = *(const float4*)(qbase + (size_t)row * QKVCOLS + 2 * CDIM + c4);
            tv.x = f2tf32(vv.x); tv.y = f2tf32(vv.y); tv.z = f2tf32(vv.z); tv.w = f2tf32(vv.w);
        }
        *(uint4*)(Ks + row * KP + c4) = tk;
        *(uint4*)(Vs + row * VP + c4) = tv;
    }
    __syncthreads();

    // ---- S = Q K^T, + bias + mask, -> Ps (float) ----
    const float* mbase = mask + (size_t)(b & (LWIN - 1)) * NTOK * NTOK;
    const float* bbase = g_bias + (size_t)h * NTOK * NTOK;

#pragma unroll
    for (int mi = 0; mi < 2; mi++) {
        float acc[13][4];
#pragma unroll
        for (int ni = 0; ni < 13; ni++)
#pragma unroll
            for (int r = 0; r < 4; r++) acc[ni][r] = 0.f;

        const uint32_t* a_base = Qs + (mw + mi * 16 + g) * QP + t4;
        const uint32_t* b_base = Ks + g * KP + t4;
#pragma unroll
        for (int ks = 0; ks < 4; ks++) {
            const int k0 = ks * 8;
            uint32_t a0 = a_base[k0], a1 = a_base[8 * QP + k0];
            uint32_t a2 = a_base[k0 + 4], a3 = a_base[8 * QP + k0 + 4];
#pragma unroll
            for (int ni = 0; ni < 13; ni++) {
                uint32_t b0 = b_base[ni * 8 * KP + k0];
                uint32_t b1 = b_base[ni * 8 * KP + k0 + 4];
                mma_tf32(acc[ni][0], acc[ni][1], acc[ni][2], acc[ni][3],
                         a0, a1, a2, a3, b0, b1);
            }
        }

        const int r0 = mw + mi * 16 + g;
        const int r1 = r0 + 8;
#pragma unroll
        for (int ni = 0; ni < 13; ni++) {
            int col = ni * 8 + 2 * t4;
            float2 v0 = make_float2(acc[ni][0], acc[ni][1]);
            float2 v1 = make_float2(acc[ni][2], acc[ni][3]);
            if (col + 1 < NTOK) {
                if (r0 < NTOK) {
                    const float* bp = bbase + r0 * NTOK + col;
                    const float* mp = mbase + r0 * NTOK + col;
                    v0.x += bp[0] + mp[0];
                    v0.y += bp[1] + mp[1];
                }
                if (r1 < NTOK) {
                    const float* bp = bbase + r1 * NTOK + col;
                    const float* mp = mbase + r1 * NTOK + col;
                    v1.x += bp[0] + mp[0];
                    v1.y += bp[1] + mp[1];
                }
            }
            *(float2*)((float*)Ps + r0 * PP + col) = v0;
            *(float2*)((float*)Ps + r1 * PP + col) = v1;
        }
    }
    __syncthreads();

    // ---- softmax rows (thread n owns row n), convert to tf32 in place ----
    if (tid < NTOK) {
        float* row = (float*)Ps + tid * PP;
        float mx = -1e30f;
        for (int m = 0; m < NTOK; m++) mx = fmaxf(mx, row[m]);
        float sum = 0.f;
        for (int m = 0; m < NTOK; m++) {
            float p = __expf(row[m] - mx);
            row[m] = p;
            sum += p;
        }
        float inv = 1.f / sum;
        uint32_t* urow = Ps + tid * PP;
        for (int m = 0; m < NTOK; m++) urow[m] = f2tf32(row[m] * inv);
        for (int m = NTOK; m < 104; m++) urow[m] = 0u;
    }
    __syncthreads();

    // ---- out = P V ----
    float* cbase = ctx + ((size_t)b * NTOK) * CDIM + h * HD;
#pragma unroll
    for (int mi = 0; mi < 2; mi++) {
        float acc[4][4];
#pragma unroll
        for (int nj = 0; nj < 4; nj++)
#pragma unroll
            for (int r = 0; r < 4; r++) acc[nj][r] = 0.f;

        const uint32_t* a_base = Ps + (mw + mi * 16 + g) * PP + t4;
#pragma unroll
        for (int ks = 0; ks < 13; ks++) {
            const int k0 = ks * 8;
            uint32_t a0 = a_base[k0], a1 = a_base[8 * PP + k0];
            uint32_t a2 = a_base[k0 + 4], a3 = a_base[8 * PP + k0 + 4];
            const uint32_t* vb = Vs + (k0 + t4) * VP + g;
#pragma unroll
            for (int nj = 0; nj < 4; nj++) {
                uint32_t b0 = vb[nj * 8];
                uint32_t b1 = vb[4 * VP + nj * 8];
                mma_tf32(acc[nj][0], acc[nj][1], acc[nj][2], acc[nj][3],
                         a0, a1, a2, a3, b0, b1);
            }
        }

        const int r0 = mw + mi * 16 + g;
        const int r1 = r0 + 8;
#pragma unroll
        for (int nj = 0; nj < 4; nj++) {
            int col = nj * 8 + 2 * t4;
            if (r0 < NTOK)
                *(float2*)(cbase + (size_t)r0 * CDIM + col) =
                    make_float2(acc[nj][0], acc[nj][1]);
            if (r1 < NTOK)
                *(float2*)(cbase + (size_t)r1 * CDIM + col) =
                    make_float2(acc[nj][2], acc[nj][3]);
        }
    }
}

// ---------------------------------------------------------------------------
// Launch
// ---------------------------------------------------------------------------
extern "C" void kernel_launch(void* const* d_in, const int* in_sizes, int n_in,
                              void* d_out, int out_size) {
    const float* x      = (const float*)d_in[0];
    const float* mask   = (const float*)d_in[1];
    const float* qkv_w  = (const float*)d_in[2];
    const float* qkv_b  = (const float*)d_in[3];
    const float* rpe    = (const float*)d_in[4];
    const float* proj_w = (const float*)d_in[5];
    const float* proj_b = (const float*)d_in[6];
    float* out = (float*)d_out;

    float *qkv_buf, *ctx_buf;
    cudaGetSymbolAddress((void**)&qkv_buf, g_qkv);
    cudaGetSymbolAddress((void**)&ctx_buf, g_ctx);

    cudaFuncSetAttribute(gemm_tf32_kernel,
                         cudaFuncAttributeMaxDynamicSharedMemorySize, GSMEM);
    cudaFuncSetAttribute(attn_mma_kernel,
                         cudaFuncAttributeMaxDynamicSharedMemorySize, ASMEM);

    // 0) bias table
    {
        int total = NHEADS * NTOK * NTOK;
        bias_kernel<<<(total + 255) / 256, 256>>>(rpe);
    }
    // 1) QKV GEMM (tf32 mma.sync): [200704,128] @ [384,128]^T
    gemm_tf32_kernel<<<MROWS / 128, 256, GSMEM>>>(x, qkv_w, qkv_b, qkv_buf, QKVCOLS);
    // 2) attention (tensor cores)
    {
        dim3 grid(BATCH, NHEADS);
        attn_mma_kernel<<<grid, 128, ASMEM>>>(qkv_buf, mask, ctx_buf);
    }
    // 3) projection GEMM (tf32): [200704,128] @ [128,128]^T -> d_out
    gemm_tf32_kernel<<<MROWS / 128, 256, GSMEM>>>(ctx_buf, proj_w, proj_b, out, CDIM);
}

// round 10
// speedup vs baseline: 2.8336x; 1.3982x over previous
#include <cuda_runtime.h>
#include <cuda_bf16.h>
#include <cstdint>

// Problem constants
#define BATCH   2048
#define NTOK    98
#define CDIM    128
#define NHEADS  4
#define HD      32
#define LWIN    512
#define MROWS   (BATCH * NTOK)          // 200704
#define QKVCOLS (3 * CDIM)              // 384
#define RELM    507                     // 3*13*13

// Scratch (allocation-free rule: __device__ globals)
__device__ float g_qkv[(size_t)MROWS * QKVCOLS];   // [B*N, 3*H*HD]
__device__ float g_ctx[(size_t)MROWS * CDIM];      // [B, N, H*HD]
__device__ float g_bias[NHEADS * NTOK * NTOK];     // [h][n][m]

__device__ __forceinline__ uint32_t f2tf32(float f) {
    uint32_t u;
    asm("cvt.rna.tf32.f32 %0, %1;" : "=r"(u) : "f"(f));
    return u;
}

extern __shared__ char smem_raw[];

__device__ __forceinline__ void mma_tf32(float& c0, float& c1, float& c2, float& c3,
                                         uint32_t a0, uint32_t a1, uint32_t a2, uint32_t a3,
                                         uint32_t b0, uint32_t b1) {
    asm volatile(
        "mma.sync.aligned.m16n8k8.row.col.f32.tf32.tf32.f32 "
        "{%0,%1,%2,%3}, {%4,%5,%6,%7}, {%8,%9}, {%0,%1,%2,%3};"
        : "+f"(c0), "+f"(c1), "+f"(c2), "+f"(c3)
        : "r"(a0), "r"(a1), "r"(a2), "r"(a3), "r"(b0), "r"(b1));
}

// ---------------------------------------------------------------------------
// Kernel 0: rel-pos bias table
// ---------------------------------------------------------------------------
__global__ void bias_kernel(const float* __restrict__ rpe) {
    int idx = blockIdx.x * blockDim.x + threadIdx.x;
    const int total = NHEADS * NTOK * NTOK;
    if (idx >= total) return;
    int m = idx % NTOK;
    int n = (idx / NTOK) % NTOK;
    int h = idx / (NTOK * NTOK);
    int tn = n / 49, rn = n % 49, hn = rn / 7, wn = rn % 7;
    int tm = m / 49, rm = m % 49, hm = rm / 7, wm = rm % 7;
    int rel = (tn - tm + 1) * 169 + (hn - hm + 6) * 13 + (wn - wm + 6);
    g_bias[idx] = rpe[h * RELM + rel];
}

// ---------------------------------------------------------------------------
// tf32 mma.sync GEMM: C[M,Ntot] = A[M,128] @ W[Ntot,128]^T + bias[Ntot]
// (unchanged from R8 — proven at 75us for proj)
// ---------------------------------------------------------------------------
#define AP 132
#define AS_FLOATS (128 * AP)
#define WS_FLOATS (64 * AP)
#define GSMEM ((AS_FLOATS + WS_FLOATS) * 4)   // 101376 bytes

__global__ void __launch_bounds__(256)
gemm_tf32_kernel(const float* __restrict__ A, const float* __restrict__ W,
                 const float* __restrict__ bias, float* __restrict__ C,
                 int Ntot) {
    uint32_t* As = (uint32_t*)smem_raw;
    uint32_t* Ws = (uint32_t*)smem_raw + AS_FLOATS;

    const int tid = threadIdx.x;
    const int wid = tid >> 5;
    const int lane = tid & 31;
    const int g = lane >> 2;
    const int t4 = lane & 3;
    const int mw = (wid & 3) * 32;
    const int nw = (wid >> 2) * 32;
    const int bm = blockIdx.x * 128;
    const int nt = Ntot >> 6;

    for (int i = 0; i < 16; i++) {
        int idx = tid + i * 256;
        int row = idx >> 5;
        int c4 = idx & 31;
        float4 v = *(const float4*)(A + (size_t)(bm + row) * CDIM + c4 * 4);
        uint4 t;
        t.x = f2tf32(v.x); t.y = f2tf32(v.y); t.z = f2tf32(v.z); t.w = f2tf32(v.w);
        *(uint4*)(As + row * AP + c4 * 4) = t;
    }

    for (int t = 0; t < nt; t++) {
        const int bn = t * 64;
        for (int i = 0; i < 8; i++) {
            int idx = tid + i * 256;
            int row = idx >> 5;
            int c4 = idx & 31;
            float4 v = *(const float4*)(W + (size_t)(bn + row) * CDIM + c4 * 4);
            uint4 u;
            u.x = f2tf32(v.x); u.y = f2tf32(v.y); u.z = f2tf32(v.z); u.w = f2tf32(v.w);
            *(uint4*)(Ws + row * AP + c4 * 4) = u;
        }
        __syncthreads();

        float acc[2][4][4];
#pragma unroll
        for (int mi = 0; mi < 2; mi++)
#pragma unroll
            for (int ni = 0; ni < 4; ni++)
#pragma unroll
                for (int r = 0; r < 4; r++) acc[mi][ni][r] = 0.f;

        const uint32_t* a_base0 = As + (mw + g) * AP + t4;
        const uint32_t* a_base1 = As + (mw + 16 + g) * AP + t4;
        const uint32_t* b_base = Ws + (nw + g) * AP + t4;

#pragma unroll
        for (int k0 = 0; k0 < 128; k0 += 8) {
            uint32_t a[2][4];
            a[0][0] = a_base0[k0];           a[0][1] = a_base0[8 * AP + k0];
            a[0][2] = a_base0[k0 + 4];       a[0][3] = a_base0[8 * AP + k0 + 4];
            a[1][0] = a_base1[k0];           a[1][1] = a_base1[8 * AP + k0];
            a[1][2] = a_base1[k0 + 4];       a[1][3] = a_base1[8 * AP + k0 + 4];
            uint32_t b[4][2];
#pragma unroll
            for (int ni = 0; ni < 4; ni++) {
                b[ni][0] = b_base[ni * 8 * AP + k0];
                b[ni][1] = b_base[ni * 8 * AP + k0 + 4];
            }
#pragma unroll
            for (int mi = 0; mi < 2; mi++)
#pragma unroll
                for (int ni = 0; ni < 4; ni++)
                    mma_tf32(acc[mi][ni][0], acc[mi][ni][1], acc[mi][ni][2], acc[mi][ni][3],
                             a[mi][0], a[mi][1], a[mi][2], a[mi][3],
                             b[ni][0], b[ni][1]);
        }

#pragma unroll
        for (int mi = 0; mi < 2; mi++) {
            int row0 = bm + mw + mi * 16 + g;
#pragma unroll
            for (int ni = 0; ni < 4; ni++) {
                int col = bn + nw + ni * 8 + 2 * t4;
                float b0 = bias[col], b1 = bias[col + 1];
                float2 v0 = make_float2(acc[mi][ni][0] + b0, acc[mi][ni][1] + b1);
                float2 v1 = make_float2(acc[mi][ni][2] + b0, acc[mi][ni][3] + b1);
                *(float2*)(C + (size_t)row0 * Ntot + col) = v0;
                *(float2*)(C + (size_t)(row0 + 8) * Ntot + col) = v1;
            }
        }
        __syncthreads();
    }
}

// ---------------------------------------------------------------------------
// Tensor-core attention v2: one CTA (256 thr, 8 warps) per (b,h).
// Warp w owns S rows 16w..16w+15. Bias+mask pre-staged into Ps (coalesced).
// Softmax: 2 threads/row, shfl-combine, unnormalized P (rowinv scaling in PV).
// ---------------------------------------------------------------------------
#define QP 36
#define KP 36
#define VP 36
#define PP 108
#define QS_OFF 0
#define KS_OFF (128 * QP)                  // 4608
#define VS_OFF (KS_OFF + 104 * KP)         // 8352
#define PS_OFF (VS_OFF + 104 * VP)         // 12096
#define RI_OFF (PS_OFF + 128 * PP)         // 25920
#define ASMEM  ((RI_OFF + 128) * 4)        // 104192 bytes

__global__ void __launch_bounds__(256)
attn_mma_kernel(const float* __restrict__ qkv, const float* __restrict__ mask,
                float* __restrict__ ctx) {
    uint32_t* Qs = (uint32_t*)smem_raw + QS_OFF;
    uint32_t* Ks = (uint32_t*)smem_raw + KS_OFF;
    uint32_t* Vs = (uint32_t*)smem_raw + VS_OFF;
    uint32_t* Ps = (uint32_t*)smem_raw + PS_OFF;
    float* Psf = (float*)Ps;
    float* rowinv = (float*)smem_raw + RI_OFF;

    const int b = blockIdx.x;
    const int h = blockIdx.y;
    const int tid = threadIdx.x;
    const int wid = tid >> 5;
    const int lane = tid & 31;
    const int g = lane >> 2;
    const int t4 = lane & 3;
    const int mw = wid * 16;              // warp's 16-row S slice
    const float scale = 0.17677669529663687f;  // 32^-0.5

    const float* qbase = qkv + (size_t)b * NTOK * QKVCOLS + h * HD;
    const float* mbase = mask + (size_t)(b & (LWIN - 1)) * NTOK * NTOK;
    const float* bbase = g_bias + (size_t)h * NTOK * NTOK;

    // Stage Q (scaled, rows padded to 128 with zeros): 1024 uint4 slots
    for (int i = tid; i < 128 * 8; i += 256) {
        int row = i >> 3;
        int c4 = (i & 7) * 4;
        uint4 t = make_uint4(0u, 0u, 0u, 0u);
        if (row < NTOK) {
            float4 v = *(const float4*)(qbase + (size_t)row * QKVCOLS + c4);
            t.x = f2tf32(v.x * scale); t.y = f2tf32(v.y * scale);
            t.z = f2tf32(v.z * scale); t.w = f2tf32(v.w * scale);
        }
        *(uint4*)(Qs + row * QP + c4) = t;
    }
    // Stage K, V (rows padded to 104 with zeros): 832 slots each
    for (int i = tid; i < 104 * 8; i += 256) {
        int row = i >> 3;
        int c4 = (i & 7) * 4;
        uint4 tk = make_uint4(0u, 0u, 0u, 0u);
        uint4 tv = make_uint4(0u, 0u, 0u, 0u);
        if (row < NTOK) {
            float4 kv = *(const float4*)(qbase + (size_t)row * QKVCOLS + CDIM + c4);
            tk.x = f2tf32(kv.x); tk.y = f2tf32(kv.y); tk.z = f2tf32(kv.z); tk.w = f2tf32(kv.w);
            float4 vv = *(const float4*)(qbase + (size_t)row * QKVCOLS + 2 * CDIM + c4);
            tv.x = f2tf32(vv.x); tv.y = f2tf32(vv.y); tv.z = f2tf32(vv.z); tv.w = f2tf32(vv.w);
        }
        *(uint4*)(Ks + row * KP + c4) = tk;
        *(uint4*)(Vs + row * VP + c4) = tv;
    }
    // Stage bias+mask into Ps (coalesced linear read of both 9604-float blocks)
    for (int i = tid; i < NTOK * NTOK; i += 256) {
        int r = i / NTOK;
        int c = i - r * NTOK;
        Psf[r * PP + c] = bbase[i] + mbase[i];
    }
    __syncthreads();

    // ---- S = Q K^T + (bias+mask already in Ps) -> Ps ----
    {
        float acc[13][4];
#pragma unroll
        for (int ni = 0; ni < 13; ni++)
#pragma unroll
            for (int r = 0; r < 4; r++) acc[ni][r] = 0.f;

        const uint32_t* a_base = Qs + (mw + g) * QP + t4;
        const uint32_t* b_base = Ks + g * KP + t4;
#pragma unroll
        for (int ks = 0; ks < 4; ks++) {
            const int k0 = ks * 8;
            uint32_t a0 = a_base[k0], a1 = a_base[8 * QP + k0];
            uint32_t a2 = a_base[k0 + 4], a3 = a_base[8 * QP + k0 + 4];
#pragma unroll
            for (int ni = 0; ni < 13; ni++) {
                uint32_t b0 = b_base[ni * 8 * KP + k0];
                uint32_t b1 = b_base[ni * 8 * KP + k0 + 4];
                mma_tf32(acc[ni][0], acc[ni][1], acc[ni][2], acc[ni][3],
                         a0, a1, a2, a3, b0, b1);
            }
        }

        const int r0 = mw + g;
        const int r1 = r0 + 8;
#pragma unroll
        for (int ni = 0; ni < 13; ni++) {
            int col = ni * 8 + 2 * t4;
            float2 p0 = *(float2*)(Psf + r0 * PP + col);
            float2 p1 = *(float2*)(Psf + r1 * PP + col);
            *(float2*)(Psf + r0 * PP + col) =
                make_float2(acc[ni][0] + p0.x, acc[ni][1] + p0.y);
            *(float2*)(Psf + r1 * PP + col) =
                make_float2(acc[ni][2] + p1.x, acc[ni][3] + p1.y);
        }
    }
    __syncthreads();

    // ---- softmax: 2 threads per row (halves of 49), unnormalized exp ----
    {
        const int row = tid >> 1;           // 0..127
        const int h2 = tid & 1;
        float* prow = Psf + row * PP + h2 * 49;
        float mx = -1e30f;
#pragma unroll 7
        for (int m = 0; m < 49; m++) mx = fmaxf(mx, prow[m]);
        mx = fmaxf(mx, __shfl_xor_sync(0xffffffffu, mx, 1));
        float sum = 0.f;
        uint32_t* urow = (uint32_t*)prow;
#pragma unroll 7
        for (int m = 0; m < 49; m++) {
            float p = __expf(prow[m] - mx);
            sum += p;
            urow[m] = f2tf32(p);
        }
        sum += __shfl_xor_sync(0xffffffffu, sum, 1);
        if (h2 == 0) rowinv[row] = 1.f / sum;
        else {
            // zero pad cols 98..103 (K-padding for PV)
            uint32_t* z = Ps + row * PP + 98;
            z[0] = 0u; z[1] = 0u; z[2] = 0u; z[3] = 0u; z[4] = 0u; z[5] = 0u;
        }
    }
    __syncthreads();

    // ---- out = (P V) * rowinv ----
    {
        float acc[4][4];
#pragma unroll
        for (int nj = 0; nj < 4; nj++)
#pragma unroll
            for (int r = 0; r < 4; r++) acc[nj][r] = 0.f;

        const uint32_t* a_base = Ps + (mw + g) * PP + t4;
#pragma unroll
        for (int ks = 0; ks < 13; ks++) {
            const int k0 = ks * 8;
            uint32_t a0 = a_base[k0], a1 = a_base[8 * PP + k0];
            uint32_t a2 = a_base[k0 + 4], a3 = a_base[8 * PP + k0 + 4];
            const uint32_t* vb = Vs + (k0 + t4) * VP + g;
#pragma unroll
            for (int nj = 0; nj < 4; nj++) {
                uint32_t b0 = vb[nj * 8];
                uint32_t b1 = vb[4 * VP + nj * 8];
                mma_tf32(acc[nj][0], acc[nj][1], acc[nj][2], acc[nj][3],
                         a0, a1, a2, a3, b0, b1);
            }
        }

        float* cbase = ctx + ((size_t)b * NTOK) * CDIM + h * HD;
        const int r0 = mw + g;
        const int r1 = r0 + 8;
        const float i0 = rowinv[r0];
        const float i1 = rowinv[r1];
#pragma unroll
        for (int nj = 0; nj < 4; nj++) {
            int col = nj * 8 + 2 * t4;
            if (r0 < NTOK)
                *(float2*)(cbase + (size_t)r0 * CDIM + col) =
                    make_float2(acc[nj][0] * i0, acc[nj][1] * i0);
            if (r1 < NTOK)
                *(float2*)(cbase + (size_t)r1 * CDIM + col) =
                    make_float2(acc[nj][2] * i1, acc[nj][3] * i1);
        }
    }
}

// ---------------------------------------------------------------------------
// Launch
// ---------------------------------------------------------------------------
extern "C" void kernel_launch(void* const* d_in, const int* in_sizes, int n_in,
                              void* d_out, int out_size) {
    const float* x      = (const float*)d_in[0];
    const float* mask   = (const float*)d_in[1];
    const float* qkv_w  = (const float*)d_in[2];
    const float* qkv_b  = (const float*)d_in[3];
    const float* rpe    = (const float*)d_in[4];
    const float* proj_w = (const float*)d_in[5];
    const float* proj_b = (const float*)d_in[6];
    float* out = (float*)d_out;

    float *qkv_buf, *ctx_buf;
    cudaGetSymbolAddress((void**)&qkv_buf, g_qkv);
    cudaGetSymbolAddress((void**)&ctx_buf, g_ctx);

    cudaFuncSetAttribute(gemm_tf32_kernel,
                         cudaFuncAttributeMaxDynamicSharedMemorySize, GSMEM);
    cudaFuncSetAttribute(attn_mma_kernel,
                         cudaFuncAttributeMaxDynamicSharedMemorySize, ASMEM);

    // 0) bias table
    {
        int total = NHEADS * NTOK * NTOK;
        bias_kernel<<<(total + 255) / 256, 256>>>(rpe);
    }
    // 1) QKV GEMM (tf32 mma.sync): [200704,128] @ [384,128]^T
    gemm_tf32_kernel<<<MROWS / 128, 256, GSMEM>>>(x, qkv_w, qkv_b, qkv_buf, QKVCOLS);
    // 2) attention (tensor cores, v2)
    {
        dim3 grid(BATCH, NHEADS);
        attn_mma_kernel<<<grid, 256, ASMEM>>>(qkv_buf, mask, ctx_buf);
    }
    // 3) projection GEMM (tf32): [200704,128] @ [128,128]^T -> d_out
    gemm_tf32_kernel<<<MROWS / 128, 256, GSMEM>>>(ctx_buf, proj_w, proj_b, out, CDIM);
}

// round 14
// speedup vs baseline: 2.8756x; 1.0148x over previous
#include <cuda_runtime.h>
#include <cuda_bf16.h>
#include <cstdint>

// Problem constants
#define BATCH   2048
#define NTOK    98
#define CDIM    128
#define NHEADS  4
#define HD      32
#define LWIN    512
#define MROWS   (BATCH * NTOK)          // 200704
#define QKVCOLS (3 * CDIM)              // 384
#define RELM    507                     // 3*13*13

// Scratch (allocation-free rule: __device__ globals)
__device__ float g_qkv[(size_t)MROWS * QKVCOLS];   // [B*N, 3*H*HD]
__device__ float g_ctx[(size_t)MROWS * CDIM];      // [B, N, H*HD]
__device__ float g_bias[NHEADS * NTOK * NTOK];     // [h][n][m]

__device__ __forceinline__ uint32_t f2tf32(float f) {
    uint32_t u;
    asm("cvt.rna.tf32.f32 %0, %1;" : "=r"(u) : "f"(f));
    return u;
}

extern __shared__ char smem_raw[];

__device__ __forceinline__ void mma_tf32(float& c0, float& c1, float& c2, float& c3,
                                         uint32_t a0, uint32_t a1, uint32_t a2, uint32_t a3,
                                         uint32_t b0, uint32_t b1) {
    asm volatile(
        "mma.sync.aligned.m16n8k8.row.col.f32.tf32.tf32.f32 "
        "{%0,%1,%2,%3}, {%4,%5,%6,%7}, {%8,%9}, {%0,%1,%2,%3};"
        : "+f"(c0), "+f"(c1), "+f"(c2), "+f"(c3)
        : "r"(a0), "r"(a1), "r"(a2), "r"(a3), "r"(b0), "r"(b1));
}

// ---------------------------------------------------------------------------
// Kernel 0: rel-pos bias table
// ---------------------------------------------------------------------------
__global__ void bias_kernel(const float* __restrict__ rpe) {
    int idx = blockIdx.x * blockDim.x + threadIdx.x;
    const int total = NHEADS * NTOK * NTOK;
    if (idx >= total) return;
    int m = idx % NTOK;
    int n = (idx / NTOK) % NTOK;
    int h = idx / (NTOK * NTOK);
    int tn = n / 49, rn = n % 49, hn = rn / 7, wn = rn % 7;
    int tm = m / 49, rm = m % 49, hm = rm / 7, wm = rm % 7;
    int rel = (tn - tm + 1) * 169 + (hn - hm + 6) * 13 + (wn - wm + 6);
    g_bias[idx] = rpe[h * RELM + rel];
}

// ---------------------------------------------------------------------------
// tf32 mma.sync GEMM: C[M,Ntot] = A[M,128] @ W[Ntot,128]^T + bias[Ntot]
// (unchanged — proven at ~75us for proj)
// ---------------------------------------------------------------------------
#define AP 132
#define AS_FLOATS (128 * AP)
#define WS_FLOATS (64 * AP)
#define GSMEM ((AS_FLOATS + WS_FLOATS) * 4)   // 101376 bytes

__global__ void __launch_bounds__(256)
gemm_tf32_kernel(const float* __restrict__ A, const float* __restrict__ W,
                 const float* __restrict__ bias, float* __restrict__ C,
                 int Ntot) {
    uint32_t* As = (uint32_t*)smem_raw;
    uint32_t* Ws = (uint32_t*)smem_raw + AS_FLOATS;

    const int tid = threadIdx.x;
    const int wid = tid >> 5;
    const int lane = tid & 31;
    const int g = lane >> 2;
    const int t4 = lane & 3;
    const int mw = (wid & 3) * 32;
    const int nw = (wid >> 2) * 32;
    const int bm = blockIdx.x * 128;
    const int nt = Ntot >> 6;

    for (int i = 0; i < 16; i++) {
        int idx = tid + i * 256;
        int row = idx >> 5;
        int c4 = idx & 31;
        float4 v = *(const float4*)(A + (size_t)(bm + row) * CDIM + c4 * 4);
        uint4 t;
        t.x = f2tf32(v.x); t.y = f2tf32(v.y); t.z = f2tf32(v.z); t.w = f2tf32(v.w);
        *(uint4*)(As + row * AP + c4 * 4) = t;
    }

    for (int t = 0; t < nt; t++) {
        const int bn = t * 64;
        for (int i = 0; i < 8; i++) {
            int idx = tid + i * 256;
            int row = idx >> 5;
            int c4 = idx & 31;
            float4 v = *(const float4*)(W + (size_t)(bn + row) * CDIM + c4 * 4);
            uint4 u;
            u.x = f2tf32(v.x); u.y = f2tf32(v.y); u.z = f2tf32(v.z); u.w = f2tf32(v.w);
            *(uint4*)(Ws + row * AP + c4 * 4) = u;
        }
        __syncthreads();

        float acc[2][4][4];
#pragma unroll
        for (int mi = 0; mi < 2; mi++)
#pragma unroll
            for (int ni = 0; ni < 4; ni++)
#pragma unroll
                for (int r = 0; r < 4; r++) acc[mi][ni][r] = 0.f;

        const uint32_t* a_base0 = As + (mw + g) * AP + t4;
        const uint32_t* a_base1 = As + (mw + 16 + g) * AP + t4;
        const uint32_t* b_base = Ws + (nw + g) * AP + t4;

#pragma unroll
        for (int k0 = 0; k0 < 128; k0 += 8) {
            uint32_t a[2][4];
            a[0][0] = a_base0[k0];           a[0][1] = a_base0[8 * AP + k0];
            a[0][2] = a_base0[k0 + 4];       a[0][3] = a_base0[8 * AP + k0 + 4];
            a[1][0] = a_base1[k0];           a[1][1] = a_base1[8 * AP + k0];
            a[1][2] = a_base1[k0 + 4];       a[1][3] = a_base1[8 * AP + k0 + 4];
            uint32_t b[4][2];
#pragma unroll
            for (int ni = 0; ni < 4; ni++) {
                b[ni][0] = b_base[ni * 8 * AP + k0];
                b[ni][1] = b_base[ni * 8 * AP + k0 + 4];
            }
#pragma unroll
            for (int mi = 0; mi < 2; mi++)
#pragma unroll
                for (int ni = 0; ni < 4; ni++)
                    mma_tf32(acc[mi][ni][0], acc[mi][ni][1], acc[mi][ni][2], acc[mi][ni][3],
                             a[mi][0], a[mi][1], a[mi][2], a[mi][3],
                             b[ni][0], b[ni][1]);
        }

#pragma unroll
        for (int mi = 0; mi < 2; mi++) {
            int row0 = bm + mw + mi * 16 + g;
#pragma unroll
            for (int ni = 0; ni < 4; ni++) {
                int col = bn + nw + ni * 8 + 2 * t4;
                float b0 = bias[col], b1 = bias[col + 1];
                float2 v0 = make_float2(acc[mi][ni][0] + b0, acc[mi][ni][1] + b1);
                float2 v1 = make_float2(acc[mi][ni][2] + b0, acc[mi][ni][3] + b1);
                *(float2*)(C + (size_t)row0 * Ntot + col) = v0;
                *(float2*)(C + (size_t)(row0 + 8) * Ntot + col) = v1;
            }
        }
        __syncthreads();
    }
}

// ---------------------------------------------------------------------------
// Tensor-core attention v3: one CTA (256 thr, 8 warps) per (b,h).
// Warps 0-6 own S rows 16w..16w+15 (112 rows >= 98). Softmax fused into the
// S epilogue: quad-shfl row reductions, exp in registers, P written once as
// tf32 (unnormalized; rowinv applied in PV epilogue). Warp 7 works staging only.
// ---------------------------------------------------------------------------
#define QP 36
#define KP 36
#define VP 36
#define PP 108
#define QS_OFF 0
#define KS_OFF (128 * QP)                  // 4608
#define VS_OFF (KS_OFF + 104 * KP)         // 8352
#define PS_OFF (VS_OFF + 104 * VP)         // 12096
#define RI_OFF (PS_OFF + 112 * PP)         // 24192
#define ASMEM  ((RI_OFF + 128) * 4)        // 97280 bytes

__global__ void __launch_bounds__(256)
attn_mma_kernel(const float* __restrict__ qkv, const float* __restrict__ mask,
                float* __restrict__ ctx) {
    uint32_t* Qs = (uint32_t*)smem_raw + QS_OFF;
    uint32_t* Ks = (uint32_t*)smem_raw + KS_OFF;
    uint32_t* Vs = (uint32_t*)smem_raw + VS_OFF;
    uint32_t* Ps = (uint32_t*)smem_raw + PS_OFF;
    float* Psf = (float*)Ps;
    float* rowinv = (float*)smem_raw + RI_OFF;

    const int b = blockIdx.x;
    const int h = blockIdx.y;
    const int tid = threadIdx.x;
    const int wid = tid >> 5;
    const int lane = tid & 31;
    const int g = lane >> 2;
    const int t4 = lane & 3;
    const int mw = wid * 16;              // warp's 16-row S slice (warps 0-6)
    const float scale = 0.17677669529663687f;  // 32^-0.5

    const float* qbase = qkv + (size_t)b * NTOK * QKVCOLS + h * HD;
    const float* mbase = mask + (size_t)(b & (LWIN - 1)) * NTOK * NTOK;
    const float* bbase = g_bias + (size_t)h * NTOK * NTOK;

    // Stage Q (scaled, rows padded to 128 with zeros)
    for (int i = tid; i < 128 * 8; i += 256) {
        int row = i >> 3;
        int c4 = (i & 7) * 4;
        uint4 t = make_uint4(0u, 0u, 0u, 0u);
        if (row < NTOK) {
            float4 v = *(const float4*)(qbase + (size_t)row * QKVCOLS + c4);
            t.x = f2tf32(v.x * scale); t.y = f2tf32(v.y * scale);
            t.z = f2tf32(v.z * scale); t.w = f2tf32(v.w * scale);
        }
        *(uint4*)(Qs + row * QP + c4) = t;
    }
    // Stage K, V (rows padded to 104 with zeros)
    for (int i = tid; i < 104 * 8; i += 256) {
        int row = i >> 3;
        int c4 = (i & 7) * 4;
        uint4 tk = make_uint4(0u, 0u, 0u, 0u);
        uint4 tv = make_uint4(0u, 0u, 0u, 0u);
        if (row < NTOK) {
            float4 kv = *(const float4*)(qbase + (size_t)row * QKVCOLS + CDIM + c4);
            tk.x = f2tf32(kv.x); tk.y = f2tf32(kv.y); tk.z = f2tf32(kv.z); tk.w = f2tf32(kv.w);
            float4 vv = *(const float4*)(qbase + (size_t)row * QKVCOLS + 2 * CDIM + c4);
            tv.x = f2tf32(vv.x); tv.y = f2tf32(vv.y); tv.z = f2tf32(vv.z); tv.w = f2tf32(vv.w);
        }
        *(uint4*)(Ks + row * KP + c4) = tk;
        *(uint4*)(Vs + row * VP + c4) = tv;
    }
    // Stage bias+mask into Ps (linear store; pads = -1e30 so exp -> 0)
    for (int i = tid; i < 112 * PP; i += 256) {
        int r = i / PP;
        int c = i - r * PP;
        float v = -1e30f;
        if (r < NTOK && c < NTOK) v = bbase[r * NTOK + c] + mbase[r * NTOK + c];
        Psf[i] = v;
    }
    __syncthreads();

    // ---- S = Q K^T + bm; fused softmax (quad shfl); write P as tf32 ----
    if (wid < 7) {
        float acc[13][4];
#pragma unroll
        for (int ni = 0; ni < 13; ni++)
#pragma unroll
            for (int r = 0; r < 4; r++) acc[ni][r] = 0.f;

        const uint32_t* a_base = Qs + (mw + g) * QP + t4;
        const uint32_t* b_base = Ks + g * KP + t4;
#pragma unroll
        for (int ks = 0; ks < 4; ks++) {
            const int k0 = ks * 8;
            uint32_t a0 = a_base[k0], a1 = a_base[8 * QP + k0];
            uint32_t a2 = a_base[k0 + 4], a3 = a_base[8 * QP + k0 + 4];
#pragma unroll
            for (int ni = 0; ni < 13; ni++) {
                uint32_t b0 = b_base[ni * 8 * KP + k0];
                uint32_t b1 = b_base[ni * 8 * KP + k0 + 4];
                mma_tf32(acc[ni][0], acc[ni][1], acc[ni][2], acc[ni][3],
                         a0, a1, a2, a3, b0, b1);
            }
        }

        const int r0 = mw + g;
        const int r1 = r0 + 8;
        float mx0 = -3e38f, mx1 = -3e38f;
#pragma unroll
        for (int ni = 0; ni < 13; ni++) {
            int col = ni * 8 + 2 * t4;
            float2 p0 = *(float2*)(Psf + r0 * PP + col);
            float2 p1 = *(float2*)(Psf + r1 * PP + col);
            acc[ni][0] += p0.x; acc[ni][1] += p0.y;
            acc[ni][2] += p1.x; acc[ni][3] += p1.y;
            mx0 = fmaxf(mx0, fmaxf(acc[ni][0], acc[ni][1]));
            mx1 = fmaxf(mx1, fmaxf(acc[ni][2], acc[ni][3]));
        }
        mx0 = fmaxf(mx0, __shfl_xor_sync(0xffffffffu, mx0, 1));
        mx0 = fmaxf(mx0, __shfl_xor_sync(0xffffffffu, mx0, 2));
        mx1 = fmaxf(mx1, __shfl_xor_sync(0xffffffffu, mx1, 1));
        mx1 = fmaxf(mx1, __shfl_xor_sync(0xffffffffu, mx1, 2));

        float sum0 = 0.f, sum1 = 0.f;
#pragma unroll
        for (int ni = 0; ni < 13; ni++) {
            int col = ni * 8 + 2 * t4;
            float e00 = __expf(acc[ni][0] - mx0);
            float e01 = __expf(acc[ni][1] - mx0);
            float e10 = __expf(acc[ni][2] - mx1);
            float e11 = __expf(acc[ni][3] - mx1);
            sum0 += e00 + e01;
            sum1 += e10 + e11;
            *(uint2*)(Ps + r0 * PP + col) = make_uint2(f2tf32(e00), f2tf32(e01));
            *(uint2*)(Ps + r1 * PP + col) = make_uint2(f2tf32(e10), f2tf32(e11));
        }
        sum0 += __shfl_xor_sync(0xffffffffu, sum0, 1);
        sum0 += __shfl_xor_sync(0xffffffffu, sum0, 2);
        sum1 += __shfl_xor_sync(0xffffffffu, sum1, 1);
        sum1 += __shfl_xor_sync(0xffffffffu, sum1, 2);
        if (t4 == 0) {
            rowinv[r0] = 1.f / sum0;
            rowinv[r1] = 1.f / sum1;
        }
    }
    __syncthreads();

    // ---- out = (P V) * rowinv ----
    if (wid < 7) {
        float acc[4][4];
#pragma unroll
        for (int nj = 0; nj < 4; nj++)
#pragma unroll
            for (int r = 0; r < 4; r++) acc[nj][r] = 0.f;

        const uint32_t* a_base = Ps + (mw + g) * PP + t4;
#pragma unroll
        for (int ks = 0; ks < 13; ks++) {
            const int k0 = ks * 8;
            uint32_t a0 = a_base[k0], a1 = a_base[8 * PP + k0];
            uint32_t a2 = a_base[k0 + 4], a3 = a_base[8 * PP + k0 + 4];
            const uint32_t* vb = Vs + (k0 + t4) * VP + g;
#pragma unroll
            for (int nj = 0; nj < 4; nj++) {
                uint32_t b0 = vb[nj * 8];
                uint32_t b1 = vb[4 * VP + nj * 8];
                mma_tf32(acc[nj][0], acc[nj][1], acc[nj][2], acc[nj][3],
                         a0, a1, a2, a3, b0, b1);
            }
        }

        float* cbase = ctx + ((size_t)b * NTOK) * CDIM + h * HD;
        const int r0 = mw + g;
        const int r1 = r0 + 8;
        const float i0 = rowinv[r0];
        const float i1 = rowinv[r1];
#pragma unroll
        for (int nj = 0; nj < 4; nj++) {
            int col = nj * 8 + 2 * t4;
            if (r0 < NTOK)
                *(float2*)(cbase + (size_t)r0 * CDIM + col) =
                    make_float2(acc[nj][0] * i0, acc[nj][1] * i0);
            if (r1 < NTOK)
                *(float2*)(cbase + (size_t)r1 * CDIM + col) =
                    make_float2(acc[nj][2] * i1, acc[nj][3] * i1);
        }
    }
}

// ---------------------------------------------------------------------------
// Launch
// ---------------------------------------------------------------------------
extern "C" void kernel_launch(void* const* d_in, const int* in_sizes, int n_in,
                              void* d_out, int out_size) {
    const float* x      = (const float*)d_in[0];
    const float* mask   = (const float*)d_in[1];
    const float* qkv_w  = (const float*)d_in[2];
    const float* qkv_b  = (const float*)d_in[3];
    const float* rpe    = (const float*)d_in[4];
    const float* proj_w = (const float*)d_in[5];
    const float* proj_b = (const float*)d_in[6];
    float* out = (float*)d_out;

    float *qkv_buf, *ctx_buf;
    cudaGetSymbolAddress((void**)&qkv_buf, g_qkv);
    cudaGetSymbolAddress((void**)&ctx_buf, g_ctx);

    cudaFuncSetAttribute(gemm_tf32_kernel,
                         cudaFuncAttributeMaxDynamicSharedMemorySize, GSMEM);
    cudaFuncSetAttribute(attn_mma_kernel,
                         cudaFuncAttributeMaxDynamicSharedMemorySize, ASMEM);

    // 0) bias table
    {
        int total = NHEADS * NTOK * NTOK;
        bias_kernel<<<(total + 255) / 256, 256>>>(rpe);
    }
    // 1) QKV GEMM (tf32 mma.sync): [200704,128] @ [384,128]^T
    gemm_tf32_kernel<<<MROWS / 128, 256, GSMEM>>>(x, qkv_w, qkv_b, qkv_buf, QKVCOLS);
    // 2) attention (tensor cores, v3: fused softmax)
    {
        dim3 grid(BATCH, NHEADS);
        attn_mma_kernel<<<grid, 256, ASMEM>>>(qkv_buf, mask, ctx_buf);
    }
    // 3) projection GEMM (tf32): [200704,128] @ [128,128]^T -> d_out
    gemm_tf32_kernel<<<MROWS / 128, 256, GSMEM>>>(ctx_buf, proj_w, proj_b, out, CDIM);
}

// round 16
// speedup vs baseline: 3.6201x; 1.2589x over previous
#include <cuda_runtime.h>
#include <cuda_bf16.h>
#include <cstdint>

// Problem constants
#define BATCH   2048
#define NTOK    98
#define CDIM    128
#define NHEADS  4
#define HD      32
#define LWIN    512
#define MROWS   (BATCH * NTOK)          // 200704
#define QKVCOLS (3 * CDIM)              // 384
#define RELM    507                     // 3*13*13

// Scratch (allocation-free rule: __device__ globals)
__device__ float g_qkv[(size_t)MROWS * QKVCOLS];   // [B*N, 3*H*HD]
__device__ float g_ctx[(size_t)MROWS * CDIM];      // [B, N, H*HD]
__device__ float g_bias[NHEADS * NTOK * NTOK];     // [h][n][m]

__device__ __forceinline__ uint32_t f2tf32(float f) {
    uint32_t u;
    asm("cvt.rna.tf32.f32 %0, %1;" : "=r"(u) : "f"(f));
    return u;
}

extern __shared__ char smem_raw[];

__device__ __forceinline__ void mma_tf32(float& c0, float& c1, float& c2, float& c3,
                                         uint32_t a0, uint32_t a1, uint32_t a2, uint32_t a3,
                                         uint32_t b0, uint32_t b1) {
    asm volatile(
        "mma.sync.aligned.m16n8k8.row.col.f32.tf32.tf32.f32 "
        "{%0,%1,%2,%3}, {%4,%5,%6,%7}, {%8,%9}, {%0,%1,%2,%3};"
        : "+f"(c0), "+f"(c1), "+f"(c2), "+f"(c3)
        : "r"(a0), "r"(a1), "r"(a2), "r"(a3), "r"(b0), "r"(b1));
}

// ---------------------------------------------------------------------------
// Kernel 0: rel-pos bias table
// ---------------------------------------------------------------------------
__global__ void bias_kernel(const float* __restrict__ rpe) {
    int idx = blockIdx.x * blockDim.x + threadIdx.x;
    const int total = NHEADS * NTOK * NTOK;
    if (idx >= total) return;
    int m = idx % NTOK;
    int n = (idx / NTOK) % NTOK;
    int h = idx / (NTOK * NTOK);
    int tn = n / 49, rn = n % 49, hn = rn / 7, wn = rn % 7;
    int tm = m / 49, rm = m % 49, hm = rm / 7, wm = rm % 7;
    int rel = (tn - tm + 1) * 169 + (hn - hm + 6) * 13 + (wn - wm + 6);
    g_bias[idx] = rpe[h * RELM + rel];
}

// ---------------------------------------------------------------------------
// tf32 mma.sync GEMM: C[M,Ntot] = A[M,128] @ W[Ntot,128]^T + bias[Ntot]
// (unchanged — proven)
// ---------------------------------------------------------------------------
#define AP 132
#define AS_FLOATS (128 * AP)
#define WS_FLOATS (64 * AP)
#define GSMEM ((AS_FLOATS + WS_FLOATS) * 4)   // 101376 bytes

__global__ void __launch_bounds__(256)
gemm_tf32_kernel(const float* __restrict__ A, const float* __restrict__ W,
                 const float* __restrict__ bias, float* __restrict__ C,
                 int Ntot) {
    uint32_t* As = (uint32_t*)smem_raw;
    uint32_t* Ws = (uint32_t*)smem_raw + AS_FLOATS;

    const int tid = threadIdx.x;
    const int wid = tid >> 5;
    const int lane = tid & 31;
    const int g = lane >> 2;
    const int t4 = lane & 3;
    const int mw = (wid & 3) * 32;
    const int nw = (wid >> 2) * 32;
    const int bm = blockIdx.x * 128;
    const int nt = Ntot >> 6;

    for (int i = 0; i < 16; i++) {
        int idx = tid + i * 256;
        int row = idx >> 5;
        int c4 = idx & 31;
        float4 v = *(const float4*)(A + (size_t)(bm + row) * CDIM + c4 * 4);
        uint4 t;
        t.x = f2tf32(v.x); t.y = f2tf32(v.y); t.z = f2tf32(v.z); t.w = f2tf32(v.w);
        *(uint4*)(As + row * AP + c4 * 4) = t;
    }

    for (int t = 0; t < nt; t++) {
        const int bn = t * 64;
        for (int i = 0; i < 8; i++) {
            int idx = tid + i * 256;
            int row = idx >> 5;
            int c4 = idx & 31;
            float4 v = *(const float4*)(W + (size_t)(bn + row) * CDIM + c4 * 4);
            uint4 u;
            u.x = f2tf32(v.x); u.y = f2tf32(v.y); u.z = f2tf32(v.z); u.w = f2tf32(v.w);
            *(uint4*)(Ws + row * AP + c4 * 4) = u;
        }
        __syncthreads();

        float acc[2][4][4];
#pragma unroll
        for (int mi = 0; mi < 2; mi++)
#pragma unroll
            for (int ni = 0; ni < 4; ni++)
#pragma unroll
                for (int r = 0; r < 4; r++) acc[mi][ni][r] = 0.f;

        const uint32_t* a_base0 = As + (mw + g) * AP + t4;
        const uint32_t* a_base1 = As + (mw + 16 + g) * AP + t4;
        const uint32_t* b_base = Ws + (nw + g) * AP + t4;

#pragma unroll
        for (int k0 = 0; k0 < 128; k0 += 8) {
            uint32_t a[2][4];
            a[0][0] = a_base0[k0];           a[0][1] = a_base0[8 * AP + k0];
            a[0][2] = a_base0[k0 + 4];       a[0][3] = a_base0[8 * AP + k0 + 4];
            a[1][0] = a_base1[k0];           a[1][1] = a_base1[8 * AP + k0];
            a[1][2] = a_base1[k0 + 4];       a[1][3] = a_base1[8 * AP + k0 + 4];
            uint32_t b[4][2];
#pragma unroll
            for (int ni = 0; ni < 4; ni++) {
                b[ni][0] = b_base[ni * 8 * AP + k0];
                b[ni][1] = b_base[ni * 8 * AP + k0 + 4];
            }
#pragma unroll
            for (int mi = 0; mi < 2; mi++)
#pragma unroll
                for (int ni = 0; ni < 4; ni++)
                    mma_tf32(acc[mi][ni][0], acc[mi][ni][1], acc[mi][ni][2], acc[mi][ni][3],
                             a[mi][0], a[mi][1], a[mi][2], a[mi][3],
                             b[ni][0], b[ni][1]);
        }

#pragma unroll
        for (int mi = 0; mi < 2; mi++) {
            int row0 = bm + mw + mi * 16 + g;
#pragma unroll
            for (int ni = 0; ni < 4; ni++) {
                int col = bn + nw + ni * 8 + 2 * t4;
                float b0 = bias[col], b1 = bias[col + 1];
                float2 v0 = make_float2(acc[mi][ni][0] + b0, acc[mi][ni][1] + b1);
                float2 v1 = make_float2(acc[mi][ni][2] + b0, acc[mi][ni][3] + b1);
                *(float2*)(C + (size_t)row0 * Ntot + col) = v0;
                *(float2*)(C + (size_t)(row0 + 8) * Ntot + col) = v1;
            }
        }
        __syncthreads();
    }
}

// ---------------------------------------------------------------------------
// Tensor-core attention v4: one CTA (224 thr, 7 warps) per (b,h).
// Only K,V in smem (30KB). Q loaded straight into A-fragments from global.
// bias+mask loaded in fragment layout (float2). Softmax fused in registers.
// P never leaves registers: C-frag -> A-frag via intra-quad shfl permutation.
// One single barrier (after K/V staging).
// ---------------------------------------------------------------------------
#define KP 36
#define VP 36
#define KS_OFF 0
#define VS_OFF (104 * KP)                  // 3744
#define ASMEM  ((VS_OFF + 104 * VP) * 4)   // 29952 bytes

__global__ void __launch_bounds__(224)
attn_mma_kernel(const float* __restrict__ qkv, const float* __restrict__ mask,
                float* __restrict__ ctx) {
    uint32_t* Ks = (uint32_t*)smem_raw + KS_OFF;
    uint32_t* Vs = (uint32_t*)smem_raw + VS_OFF;

    const int b = blockIdx.x;
    const int h = blockIdx.y;
    const int tid = threadIdx.x;
    const int wid = tid >> 5;
    const int lane = tid & 31;
    const int g = lane >> 2;
    const int t4 = lane & 3;
    const int mw = wid * 16;              // warp's 16-row slice (7 warps = 112 rows)
    const float scale = 0.17677669529663687f;  // 32^-0.5

    const float* qbase = qkv + (size_t)b * NTOK * QKVCOLS + h * HD;
    const float* mbase = mask + (size_t)(b & (LWIN - 1)) * NTOK * NTOK;
    const float* bbase = g_bias + (size_t)h * NTOK * NTOK;

    // Stage K, V (rows padded to 104 with zeros)
    for (int i = tid; i < 104 * 8; i += 224) {
        int row = i >> 3;
        int c4 = (i & 7) * 4;
        uint4 tk = make_uint4(0u, 0u, 0u, 0u);
        uint4 tv = make_uint4(0u, 0u, 0u, 0u);
        if (row < NTOK) {
            float4 kv = *(const float4*)(qbase + (size_t)row * QKVCOLS + CDIM + c4);
            tk.x = f2tf32(kv.x); tk.y = f2tf32(kv.y); tk.z = f2tf32(kv.z); tk.w = f2tf32(kv.w);
            float4 vv = *(const float4*)(qbase + (size_t)row * QKVCOLS + 2 * CDIM + c4);
            tv.x = f2tf32(vv.x); tv.y = f2tf32(vv.y); tv.z = f2tf32(vv.z); tv.w = f2tf32(vv.w);
        }
        *(uint4*)(Ks + row * KP + c4) = tk;
        *(uint4*)(Vs + row * VP + c4) = tv;
    }

    const int r0 = mw + g;
    const int r1 = r0 + 8;

    // Q A-fragments straight from global (rows clamped; garbage rows unused)
    uint32_t qa[4][4];
    {
        const float* qr0 = qbase + (size_t)(r0 < NTOK ? r0 : NTOK - 1) * QKVCOLS;
        const float* qr1 = qbase + (size_t)(r1 < NTOK ? r1 : NTOK - 1) * QKVCOLS;
#pragma unroll
        for (int k = 0; k < 4; k++) {
            qa[k][0] = f2tf32(qr0[k * 8 + t4] * scale);
            qa[k][1] = f2tf32(qr1[k * 8 + t4] * scale);
            qa[k][2] = f2tf32(qr0[k * 8 + t4 + 4] * scale);
            qa[k][3] = f2tf32(qr1[k * 8 + t4 + 4] * scale);
        }
    }
    __syncthreads();

    // ---- S = Q K^T (13 n-tiles of 8) ----
    float acc[13][4];
#pragma unroll
    for (int ni = 0; ni < 13; ni++)
#pragma unroll
        for (int r = 0; r < 4; r++) acc[ni][r] = 0.f;

    {
        const uint32_t* b_base = Ks + g * KP + t4;
#pragma unroll
        for (int ks = 0; ks < 4; ks++) {
            const int k0 = ks * 8;
#pragma unroll
            for (int ni = 0; ni < 13; ni++) {
                uint32_t b0 = b_base[ni * 8 * KP + k0];
                uint32_t b1 = b_base[ni * 8 * KP + k0 + 4];
                mma_tf32(acc[ni][0], acc[ni][1], acc[ni][2], acc[ni][3],
                         qa[ks][0], qa[ks][1], qa[ks][2], qa[ks][3], b0, b1);
            }
        }
    }

    // ---- + bias + mask (fragment-layout float2 loads); pads -> -1e30 ----
    const bool row0_ok = (r0 < NTOK);
    const bool row1_ok = (r1 < NTOK);
#pragma unroll
    for (int ni = 0; ni < 13; ni++) {
        int col = ni * 8 + 2 * t4;
        if (col < NTOK) {
            if (row0_ok) {
                float2 bv = *(const float2*)(bbase + r0 * NTOK + col);
                float2 mv = *(const float2*)(mbase + r0 * NTOK + col);
                acc[ni][0] += bv.x + mv.x;
                acc[ni][1] += bv.y + mv.y;
            }
            if (row1_ok) {
                float2 bv = *(const float2*)(bbase + r1 * NTOK + col);
                float2 mv = *(const float2*)(mbase + r1 * NTOK + col);
                acc[ni][2] += bv.x + mv.x;
                acc[ni][3] += bv.y + mv.y;
            }
        } else {
            acc[ni][0] = -1e30f; acc[ni][1] = -1e30f;
            acc[ni][2] = -1e30f; acc[ni][3] = -1e30f;
        }
    }

    // ---- softmax in registers (quad shfl over t4) ----
    float mx0 = -3e38f, mx1 = -3e38f;
#pragma unroll
    for (int ni = 0; ni < 13; ni++) {
        mx0 = fmaxf(mx0, fmaxf(acc[ni][0], acc[ni][1]));
        mx1 = fmaxf(mx1, fmaxf(acc[ni][2], acc[ni][3]));
    }
    mx0 = fmaxf(mx0, __shfl_xor_sync(0xffffffffu, mx0, 1));
    mx0 = fmaxf(mx0, __shfl_xor_sync(0xffffffffu, mx0, 2));
    mx1 = fmaxf(mx1, __shfl_xor_sync(0xffffffffu, mx1, 1));
    mx1 = fmaxf(mx1, __shfl_xor_sync(0xffffffffu, mx1, 2));

    float sum0 = 0.f, sum1 = 0.f;
#pragma unroll
    for (int ni = 0; ni < 13; ni++) {
        acc[ni][0] = __expf(acc[ni][0] - mx0);
        acc[ni][1] = __expf(acc[ni][1] - mx0);
        acc[ni][2] = __expf(acc[ni][2] - mx1);
        acc[ni][3] = __expf(acc[ni][3] - mx1);
        sum0 += acc[ni][0] + acc[ni][1];
        sum1 += acc[ni][2] + acc[ni][3];
    }
    sum0 += __shfl_xor_sync(0xffffffffu, sum0, 1);
    sum0 += __shfl_xor_sync(0xffffffffu, sum0, 2);
    sum1 += __shfl_xor_sync(0xffffffffu, sum1, 1);
    sum1 += __shfl_xor_sync(0xffffffffu, sum1, 2);
    const float i0 = 1.f / sum0;
    const float i1 = 1.f / sum1;

    // ---- out = (P V) * rowinv; P C-frag -> A-frag via intra-quad shfl ----
    float pacc[4][4];
#pragma unroll
    for (int nj = 0; nj < 4; nj++)
#pragma unroll
        for (int r = 0; r < 4; r++) pacc[nj][r] = 0.f;

    const int src_lo = (lane & ~3) | (t4 >> 1);
    const int src_hi = src_lo + 2;
    const bool odd = (t4 & 1);

#pragma unroll
    for (int k = 0; k < 13; k++) {
        float p00 = __shfl_sync(0xffffffffu, acc[k][0], src_lo);
        float p01 = __shfl_sync(0xffffffffu, acc[k][1], src_lo);
        float p10 = __shfl_sync(0xffffffffu, acc[k][2], src_lo);
        float p11 = __shfl_sync(0xffffffffu, acc[k][3], src_lo);
        float q00 = __shfl_sync(0xffffffffu, acc[k][0], src_hi);
        float q01 = __shfl_sync(0xffffffffu, acc[k][1], src_hi);
        float q10 = __shfl_sync(0xffffffffu, acc[k][2], src_hi);
        float q11 = __shfl_sync(0xffffffffu, acc[k][3], src_hi);
        uint32_t a0 = f2tf32(odd ? p01 : p00);   // P[r0][8k+t4]
        uint32_t a1 = f2tf32(odd ? p11 : p10);   // P[r1][8k+t4]
        uint32_t a2 = f2tf32(odd ? q01 : q00);   // P[r0][8k+t4+4]
        uint32_t a3 = f2tf32(odd ? q11 : q10);   // P[r1][8k+t4+4]

        const uint32_t* vb = Vs + (k * 8 + t4) * VP + g;
#pragma unroll
        for (int nj = 0; nj < 4; nj++) {
            uint32_t b0 = vb[nj * 8];
            uint32_t b1 = vb[4 * VP + nj * 8];
            mma_tf32(pacc[nj][0], pacc[nj][1], pacc[nj][2], pacc[nj][3],
                     a0, a1, a2, a3, b0, b1);
        }
    }

    float* cbase = ctx + ((size_t)b * NTOK) * CDIM + h * HD;
#pragma unroll
    for (int nj = 0; nj < 4; nj++) {
        int col = nj * 8 + 2 * t4;
        if (row0_ok)
            *(float2*)(cbase + (size_t)r0 * CDIM + col) =
                make_float2(pacc[nj][0] * i0, pacc[nj][1] * i0);
        if (row1_ok)
            *(float2*)(cbase + (size_t)r1 * CDIM + col) =
                make_float2(pacc[nj][2] * i1, pacc[nj][3] * i1);
    }
}

// ---------------------------------------------------------------------------
// Launch
// ---------------------------------------------------------------------------
extern "C" void kernel_launch(void* const* d_in, const int* in_sizes, int n_in,
                              void* d_out, int out_size) {
    const float* x      = (const float*)d_in[0];
    const float* mask   = (const float*)d_in[1];
    const float* qkv_w  = (const float*)d_in[2];
    const float* qkv_b  = (const float*)d_in[3];
    const float* rpe    = (const float*)d_in[4];
    const float* proj_w = (const float*)d_in[5];
    const float* proj_b = (const float*)d_in[6];
    float* out = (float*)d_out;

    float *qkv_buf, *ctx_buf;
    cudaGetSymbolAddress((void**)&qkv_buf, g_qkv);
    cudaGetSymbolAddress((void**)&ctx_buf, g_ctx);

    cudaFuncSetAttribute(gemm_tf32_kernel,
                         cudaFuncAttributeMaxDynamicSharedMemorySize, GSMEM);
    cudaFuncSetAttribute(attn_mma_kernel,
                         cudaFuncAttributeMaxDynamicSharedMemorySize, ASMEM);

    // 0) bias table
    {
        int total = NHEADS * NTOK * NTOK;
        bias_kernel<<<(total + 255) / 256, 256>>>(rpe);
    }
    // 1) QKV GEMM (tf32 mma.sync): [200704,128] @ [384,128]^T
    gemm_tf32_kernel<<<MROWS / 128, 256, GSMEM>>>(x, qkv_w, qkv_b, qkv_buf, QKVCOLS);
    // 2) attention (tensor cores, v4: register-resident P, smem = K/V only)
    {
        dim3 grid(BATCH, NHEADS);
        attn_mma_kernel<<<grid, 224, ASMEM>>>(qkv_buf, mask, ctx_buf);
    }
    // 3) projection GEMM (tf32): [200704,128] @ [128,128]^T -> d_out
    gemm_tf32_kernel<<<MROWS / 128, 256, GSMEM>>>(ctx_buf, proj_w, proj_b, out, CDIM);
}